// round 2
// baseline (speedup 1.0000x reference)
#include <cuda_runtime.h>
#include <cuda_bf16.h>
#include <math.h>

// Problem constants
#define BB 4
#define CC 64
#define HH 128
#define WW 128
#define EE 32
#define HW (HH*WW)            // 16384
#define NPIX (BB*HW)          // 65536
#define NASSIGN (NPIX*2)      // 131072
#define WPERE (9*CC*CC)       // 36864 floats per expert (transposed)

// Conv kernel config
#define GP 14                 // groups per CTA
#define CONV_GRID 296         // 296*14 = 4144 >= max total groups (4128)
#define CONV_THREADS 448      // 14 warps
#define CONV_SMEM_FLOATS (WPERE + 64)   // weights + bias
#define CONV_SMEM_BYTES (CONV_SMEM_FLOATS * 4)

// -------- device scratch (no allocations allowed) --------
__device__ float g_xT[NPIX * CC];          // x channels-last [B][H][W][C]
__device__ float g_wT[EE * WPERE];         // weights [E][tap][ci][co]
__device__ int   g_top_idx[NPIX * 2];
__device__ float g_top_w[NPIX * 2];
__device__ int   g_cnt[EE];
__device__ int   g_base[EE];
__device__ int   g_cursor[EE];
__device__ int   g_groupStart[EE + 1];
__device__ int   g_listPix[NASSIGN];
__device__ float g_listW[NASSIGN];

// -------- init: zero output + counters --------
__global__ void k_init(float* out, int n) {
    int i = blockIdx.x * blockDim.x + threadIdx.x;
    if (i < n) out[i] = 0.0f;
    if (blockIdx.x == 0 && threadIdx.x < EE) {
        g_cnt[threadIdx.x] = 0;
        g_cursor[threadIdx.x] = 0;
    }
}

// -------- transpose x: [B][C][H][W] -> [B][HW][C] --------
__global__ void k_tx(const float* __restrict__ x) {
    __shared__ float s[CC][33];
    int b = blockIdx.y;
    int hw0 = blockIdx.x * 32;
    int tx = threadIdx.x;      // 0..31
    int ty = threadIdx.y;      // 0..7
    for (int c = ty; c < CC; c += 8)
        s[c][tx] = x[((size_t)(b * CC + c) << 14) + hw0 + tx];
    __syncthreads();
    int t = ty * 32 + tx;
    for (int k = t; k < 32 * CC; k += 256) {
        int hw = k >> 6, c = k & 63;
        g_xT[((size_t)(b * HW + hw0 + hw) << 6) + c] = s[c][hw];
    }
}

// -------- transpose weights: [E][co][ci][3][3] -> [E][tap][ci][co] --------
__global__ void k_tw(const float* __restrict__ w) {
    int i = blockIdx.x * 256 + threadIdx.x;
    if (i >= EE * WPERE) return;
    int co = i & 63;
    int ci = (i >> 6) & 63;
    int te = i >> 12;          // e*9 + t
    int t = te % 9;
    int e = te / 9;
    g_wT[i] = w[(((e << 6) | co) * 64 + ci) * 9 + t];
}

// -------- gate: logits, top-2, softmax, counts --------
__global__ void k_gate(const float* __restrict__ x,
                       const float* __restrict__ gw,
                       const float* __restrict__ gb) {
    __shared__ float gws[EE * CC];
    __shared__ float gbs[EE];
    int tid = threadIdx.x;
    for (int i = tid; i < EE * CC; i += 256) gws[i] = gw[i];
    if (tid < EE) gbs[tid] = gb[tid];
    __syncthreads();

    int pix = blockIdx.x * 256 + tid;
    int b = pix >> 14, hw = pix & (HW - 1);

    float lg[EE];
#pragma unroll
    for (int e = 0; e < EE; e++) lg[e] = gbs[e];

    const float* xp = x + ((size_t)b << 20) + hw;
#pragma unroll 4
    for (int c = 0; c < CC; c++) {
        float xv = xp[(size_t)c << 14];
#pragma unroll
        for (int e = 0; e < EE; e++) lg[e] = fmaf(xv, gws[e * CC + c], lg[e]);
    }

    // exact top-2 with first-index-on-tie (matches lax.top_k)
    float v1 = -1e30f; int i1 = 0;
#pragma unroll
    for (int e = 0; e < EE; e++) if (lg[e] > v1) { v1 = lg[e]; i1 = e; }
    float v2 = -1e30f; int i2 = 0;
#pragma unroll
    for (int e = 0; e < EE; e++) if (e != i1 && lg[e] > v2) { v2 = lg[e]; i2 = e; }

    float d = expf(v2 - v1);
    float s = 1.0f / (1.0f + d);
    g_top_idx[pix * 2]     = i1;
    g_top_idx[pix * 2 + 1] = i2;
    g_top_w[pix * 2]       = s;
    g_top_w[pix * 2 + 1]   = d * s;
    atomicAdd(&g_cnt[i1], 1);
    atomicAdd(&g_cnt[i2], 1);
}

// -------- prefix sums over 32 experts (trivial) --------
__global__ void k_prefix() {
    if (threadIdx.x == 0) {
        int s = 0, g = 0;
        for (int e = 0; e < EE; e++) {
            g_base[e] = s;       s += g_cnt[e];
            g_groupStart[e] = g; g += (g_cnt[e] + 31) >> 5;
        }
        g_groupStart[EE] = g;
    }
}

// -------- scatter assignments into per-expert lists --------
__global__ void k_scatter() {
    int pix = blockIdx.x * 256 + threadIdx.x;
#pragma unroll
    for (int k = 0; k < 2; k++) {
        int e = g_top_idx[pix * 2 + k];
        int pos = atomicAdd(&g_cursor[e], 1);
        int at = g_base[e] + pos;
        g_listPix[at] = pix;
        g_listW[at]   = g_top_w[pix * 2 + k];
    }
}

// -------- main sparse conv --------
__global__ void __launch_bounds__(CONV_THREADS, 1)
k_conv(const float* __restrict__ expert_b, float* __restrict__ out) {
    extern __shared__ float ws[];   // [9][64 ci][64 co] + bias[64]
    const int tid  = threadIdx.x;
    const int warp = tid >> 5;
    const int lane = tid & 31;

    const int total = g_groupStart[EE];
    int g0 = blockIdx.x * GP;
    if (g0 >= total) return;
    int g1 = g0 + GP; if (g1 > total) g1 = total;

    int e = 0;
    while (g_groupStart[e + 1] <= g0) e++;

    bool first = true;
    for (; e < EE; e++) {
        int gs = g_groupStart[e], ge = g_groupStart[e + 1];
        if (gs >= g1) break;
        int ga = g0 > gs ? g0 : gs;
        int gb = g1 < ge ? g1 : ge;
        if (ga >= gb) continue;

        if (!first) __syncthreads();
        first = false;
        {   // stage expert weights (144KB) + bias
            const float4* src = (const float4*)(g_wT + (size_t)e * WPERE);
            float4* dst = (float4*)ws;
            for (int i = tid; i < WPERE / 4; i += CONV_THREADS) dst[i] = src[i];
            if (tid < 64) ws[WPERE + tid] = expert_b[e * 64 + tid];
        }
        __syncthreads();

        const int m  = g_cnt[e];
        const int lb = g_base[e];

        for (int g = ga + warp; g < gb; g += CONV_THREADS / 32) {
            int li = (g - gs) * 32 + lane;
            bool valid = li < m;
            int idx = lb + (valid ? li : 0);
            int pix = g_listPix[idx];
            float gw = g_listW[idx];
            int b  = pix >> 14;
            int hw = pix & (HW - 1);
            int y  = hw >> 7, xw = hw & 127;

            float acc[64];
#pragma unroll
            for (int c = 0; c < 64; c++) acc[c] = 0.0f;

#pragma unroll 1
            for (int t = 0; t < 9; t++) {
                int dy = t / 3 - 1, dx = t % 3 - 1;
                int yy = y + dy, xx = xw + dx;
                if (!valid || (unsigned)yy >= (unsigned)HH || (unsigned)xx >= (unsigned)WW)
                    continue;
                const float4* __restrict__ xp =
                    (const float4*)(g_xT + ((size_t)((b << 14) + (yy << 7) + xx) << 6));
                const float4* __restrict__ wt4 = (const float4*)(ws + t * (CC * CC));
#pragma unroll 2
                for (int c4i = 0; c4i < 16; c4i++) {
                    float4 xv = xp[c4i];
#pragma unroll
                    for (int j = 0; j < 4; j++) {
                        float xs = (j == 0) ? xv.x : (j == 1) ? xv.y : (j == 2) ? xv.z : xv.w;
                        const float4* wr = wt4 + ((c4i * 4 + j) << 4);
#pragma unroll
                        for (int o = 0; o < 16; o++) {
                            float4 wv = wr[o];
                            acc[4 * o + 0] = fmaf(xs, wv.x, acc[4 * o + 0]);
                            acc[4 * o + 1] = fmaf(xs, wv.y, acc[4 * o + 1]);
                            acc[4 * o + 2] = fmaf(xs, wv.z, acc[4 * o + 2]);
                            acc[4 * o + 3] = fmaf(xs, wv.w, acc[4 * o + 3]);
                        }
                    }
                }
            }

            if (valid) {
                float* op = out + ((size_t)b << 20) + hw;
#pragma unroll
                for (int c = 0; c < 64; c++)
                    atomicAdd(op + ((size_t)c << 14), gw * (acc[c] + ws[WPERE + c]));
            }
        }
    }
}

// -------- final relu in place --------
__global__ void k_relu(float* out, int n) {
    int i = blockIdx.x * 256 + threadIdx.x;
    if (i < n) out[i] = fmaxf(out[i], 0.0f);
}

extern "C" void kernel_launch(void* const* d_in, const int* in_sizes, int n_in,
                              void* d_out, int out_size) {
    const float* x        = (const float*)d_in[0];
    const float* expert_w = (const float*)d_in[1];
    const float* expert_b = (const float*)d_in[2];
    const float* gate_w   = (const float*)d_in[3];
    const float* gate_b   = (const float*)d_in[4];
    float* out = (float*)d_out;

    cudaFuncSetAttribute(k_conv, cudaFuncAttributeMaxDynamicSharedMemorySize,
                         CONV_SMEM_BYTES);

    int n = NPIX * CC;   // 4,194,304 output elems

    k_init<<<(n + 255) / 256, 256>>>(out, n);
    k_tx<<<dim3(HW / 32, BB), dim3(32, 8)>>>(x);
    k_tw<<<(EE * WPERE + 255) / 256, 256>>>(expert_w);
    k_gate<<<NPIX / 256, 256>>>(x, gate_w, gate_b);
    k_prefix<<<1, 32>>>();
    k_scatter<<<NPIX / 256, 256>>>();
    k_conv<<<CONV_GRID, CONV_THREADS, CONV_SMEM_BYTES>>>(expert_b, out);
    k_relu<<<(n + 255) / 256, 256>>>(out, n);
}

// round 5
// speedup vs baseline: 1.9534x; 1.9534x over previous
#include <cuda_runtime.h>
#include <cuda_bf16.h>
#include <math.h>

// ---------------- problem constants ----------------
#define BB 4
#define CC 64
#define HH 128
#define WW 128
#define EE 32
#define HW (HH*WW)              // 16384
#define NPIX (BB*HW)            // 65536
#define NASSIGN (NPIX*2)        // 131072
#define PADW 130
#define PADIMG (PADW*PADW)      // 16900
#define NPADROW (BB*PADIMG)     // 67600
#define MAXTILES 1056

// per-expert pre-permuted weight fragment words: 9 taps * 4 kc * 8 nb * 32 lanes * 2 words
#define WFE 18432

// conv smem layout (byte offsets). A rows padded to 144B to kill bank conflicts.
#define AHI_OFF 0u              // 128 rows * 144B = 18432
#define ALO_OFF 18432u          // 18432
#define BHI_OFF 36864u          // 8192
#define BLO_OFF 45056u          // 8192
#define PR_OFF  53248u          // int[128]
#define GW_OFF  53760u          // float[128]
#define BIAS_OFF 54272u         // float[64]
#define CONV_SMEM 54528u

// ---------------- device scratch ----------------
__device__ __nv_bfloat16 g_x_hi[NPADROW * CC];
__device__ __nv_bfloat16 g_x_lo[NPADROW * CC];
__device__ unsigned g_wfhi[EE * WFE];    // pre-permuted B fragments (hi)
__device__ unsigned g_wflo[EE * WFE];    // pre-permuted B fragments (lo)
__device__ int   g_top_idx[NPIX * 2];
__device__ float g_top_w[NPIX * 2];
__device__ int   g_cnt[EE];
__device__ int   g_base[EE];
__device__ int   g_cursor[EE];
__device__ int   g_tileStart[EE + 1];
__device__ int   g_listPix[NASSIGN];
__device__ float g_listW[NASSIGN];

__device__ __forceinline__ unsigned short bfbits(__nv_bfloat16 h) {
    return *reinterpret_cast<unsigned short*>(&h);
}

// ---------------- init ----------------
__global__ void k_init(float* out, int n) {
    int i = blockIdx.x * blockDim.x + threadIdx.x;
    if (i < n) out[i] = 0.0f;
    if (blockIdx.x == 0 && threadIdx.x < EE) {
        g_cnt[threadIdx.x] = 0;
        g_cursor[threadIdx.x] = 0;
    }
}

// ---------------- x -> padded channels-last bf16 hi/lo ----------------
__global__ void k_tx(const float* __restrict__ x) {
    __shared__ float s[CC][33];
    int b = blockIdx.y;
    int hw0 = blockIdx.x * 32;
    int tx = threadIdx.x, ty = threadIdx.y;
    for (int c = ty; c < CC; c += 8)
        s[c][tx] = x[((size_t)(b * CC + c) << 14) + hw0 + tx];
    __syncthreads();
    int t = ty * 32 + tx;
    int y = hw0 >> 7, x0 = hw0 & 127;
    unsigned* hi32 = (unsigned*)g_x_hi;
    unsigned* lo32 = (unsigned*)g_x_lo;
    for (int k = t; k < 32 * 32; k += 256) {
        int p = k >> 5, cp = k & 31;   // pixel-in-block, channel-pair
        int row = b * PADIMG + (y + 1) * PADW + (x0 + p + 1);
        float a = s[2 * cp][p], bv = s[2 * cp + 1][p];
        __nv_bfloat16 ha = __float2bfloat16_rn(a), hb = __float2bfloat16_rn(bv);
        float la = a - __bfloat162float(ha), lb = bv - __bfloat162float(hb);
        __nv_bfloat16 hla = __float2bfloat16_rn(la), hlb = __float2bfloat16_rn(lb);
        hi32[row * 32 + cp] = ((unsigned)bfbits(hb) << 16) | bfbits(ha);
        lo32[row * 32 + cp] = ((unsigned)bfbits(hlb) << 16) | bfbits(hla);
    }
}

// ---------------- zero the halo rows ----------------
__global__ void k_border() {
    int w = blockIdx.x * 256 + threadIdx.x;
    if (w >= NPADROW * 32) return;
    int p = w >> 5;
    int r = p % PADIMG;
    int y = r / PADW, xx = r % PADW;
    if (y == 0 || y == PADW - 1 || xx == 0 || xx == PADW - 1) {
        ((unsigned*)g_x_hi)[w] = 0u;
        ((unsigned*)g_x_lo)[w] = 0u;
    }
}

// ---------------- weights -> pre-permuted mma B fragments ----------------
// B frag (m16n8k16, col): thread t word w holds {B[k0][n], B[k0+1][n]},
// k0 = 2*(t%4) + 8*w, n = t/4.  B[k][n] = weight[co=n][ci=k].
// word index: ((((e*9 + t)*4 + kc)*8 + nb)*32 + lane)*2 + w
__global__ void k_tw(const float* __restrict__ w) {
    int widx = blockIdx.x * 256 + threadIdx.x;
    if (widx >= EE * WFE) return;
    int e = widx / WFE;
    int r = widx % WFE;
    int t = r / 2048;  r %= 2048;
    int kc = r / 512;  r %= 512;
    int nb = r / 64;   r %= 64;
    int lane = r >> 1;
    int wreg = r & 1;
    int co  = nb * 8 + (lane >> 2);
    int ci0 = kc * 16 + wreg * 8 + 2 * (lane & 3);
    float v0 = w[(((e << 6) | co) * 64 + ci0) * 9 + t];
    float v1 = w[(((e << 6) | co) * 64 + ci0 + 1) * 9 + t];
    __nv_bfloat16 h0 = __float2bfloat16_rn(v0), h1 = __float2bfloat16_rn(v1);
    float l0 = v0 - __bfloat162float(h0), l1 = v1 - __bfloat162float(h1);
    g_wfhi[widx] = ((unsigned)bfbits(h1) << 16) | bfbits(h0);
    g_wflo[widx] = ((unsigned)bfbits(__float2bfloat16_rn(l1)) << 16)
                 | bfbits(__float2bfloat16_rn(l0));
}

// ---------------- gate (fp32, smem-staged) ----------------
__global__ void __launch_bounds__(256) k_gate(const float* __restrict__ x,
                                              const float* __restrict__ gw,
                                              const float* __restrict__ gb) {
    __shared__ float gws[EE * CC];
    __shared__ float gbs[EE];
    __shared__ float xs[16][256];
    int tid = threadIdx.x;
    for (int i = tid; i < EE * CC; i += 256) gws[i] = gw[i];
    if (tid < EE) gbs[tid] = gb[tid];

    int pix0 = blockIdx.x * 256;
    int b = pix0 >> 14, hw0 = pix0 & (HW - 1);

    float lg[EE];
#pragma unroll
    for (int e = 0; e < EE; e++) lg[e] = 0.0f;

    for (int c0 = 0; c0 < CC; c0 += 16) {
        __syncthreads();
        for (int i = tid; i < 16 * 256; i += 256)
            xs[i >> 8][tid] = x[((size_t)(b * CC + c0 + (i >> 8)) << 14) + hw0 + tid];
        __syncthreads();
#pragma unroll 4
        for (int c = 0; c < 16; c++) {
            float xv = xs[c][tid];
#pragma unroll
            for (int e = 0; e < EE; e++)
                lg[e] = fmaf(xv, gws[(e << 6) + c0 + c], lg[e]);
        }
    }
#pragma unroll
    for (int e = 0; e < EE; e++) lg[e] += gbs[e];

    // exact top-2, first-index-on-tie (matches lax.top_k)
    float v1 = -1e30f; int i1 = 0;
#pragma unroll
    for (int e = 0; e < EE; e++) if (lg[e] > v1) { v1 = lg[e]; i1 = e; }
    float v2 = -1e30f; int i2 = 0;
#pragma unroll
    for (int e = 0; e < EE; e++) if (e != i1 && lg[e] > v2) { v2 = lg[e]; i2 = e; }

    float d = expf(v2 - v1);
    float s = 1.0f / (1.0f + d);
    int pix = pix0 + tid;
    g_top_idx[pix * 2]     = i1;
    g_top_idx[pix * 2 + 1] = i2;
    g_top_w[pix * 2]       = s;
    g_top_w[pix * 2 + 1]   = d * s;
    atomicAdd(&g_cnt[i1], 1);
    atomicAdd(&g_cnt[i2], 1);
}

// ---------------- prefix ----------------
__global__ void k_prefix() {
    if (threadIdx.x == 0) {
        int s = 0, t = 0;
        for (int e = 0; e < EE; e++) {
            g_base[e] = s;      s += g_cnt[e];
            g_tileStart[e] = t; t += (g_cnt[e] + 127) >> 7;
        }
        g_tileStart[EE] = t;
    }
}

// ---------------- scatter ----------------
__global__ void k_scatter() {
    int pix = blockIdx.x * 256 + threadIdx.x;
#pragma unroll
    for (int k = 0; k < 2; k++) {
        int e = g_top_idx[pix * 2 + k];
        int pos = atomicAdd(&g_cursor[e], 1);
        int at = g_base[e] + pos;
        g_listPix[at] = pix;
        g_listW[at]   = g_top_w[pix * 2 + k];
    }
}

// ---------------- main conv: mma.sync bf16 3-pass ----------------
#define MMA(c, a, b0, b1) \
    asm volatile("mma.sync.aligned.m16n8k16.row.col.f32.bf16.bf16.f32 " \
        "{%0,%1,%2,%3}, {%4,%5,%6,%7}, {%8,%9}, {%0,%1,%2,%3};" \
        : "+f"((c)[0]), "+f"((c)[1]), "+f"((c)[2]), "+f"((c)[3]) \
        : "r"((a)[0]), "r"((a)[1]), "r"((a)[2]), "r"((a)[3]), "r"(b0), "r"(b1))

__global__ void __launch_bounds__(256, 2)
k_conv(const float* __restrict__ expert_b, float* __restrict__ out) {
    extern __shared__ char sm[];
    const int tid = threadIdx.x, warp = tid >> 5, lane = tid & 31;

    int tile = blockIdx.x;
    if (tile >= g_tileStart[EE]) return;

    int e = 0;
    while (g_tileStart[e + 1] <= tile) e++;
    int r0 = (tile - g_tileStart[e]) << 7;
    int m  = g_cnt[e] - r0; if (m > 128) m = 128;
    int lb = g_base[e] + r0;

    // pixel padded-row indices + gate weights + bias
    if (tid < 128) {
        int valid = tid < m;
        int idx = lb + (valid ? tid : 0);
        int pix = g_listPix[idx];
        float gv = valid ? g_listW[idx] : 0.0f;
        // invalid lanes park on interior pixel (0,0): all 9 taps in-bounds
        int row = PADW + 1;
        if (valid) {
            int b = pix >> 14, hw = pix & (HW - 1);
            row = b * PADIMG + ((hw >> 7) + 1) * PADW + ((hw & 127) + 1);
        }
        ((int*)(sm + PR_OFF))[tid]   = row;
        ((float*)(sm + GW_OFF))[tid] = gv;
    }
    if (tid < 64) ((float*)(sm + BIAS_OFF))[tid] = expert_b[(e << 6) + tid];
    __syncthreads();

    const int myrow = tid >> 1, half = tid & 1;
    const int rbase = ((int*)(sm + PR_OFF))[myrow];
    const uint4* __restrict__ wfh4 = (const uint4*)(g_wfhi + (size_t)e * WFE);
    const uint4* __restrict__ wfl4 = (const uint4*)(g_wflo + (size_t)e * WFE);

    float c[8][4];
#pragma unroll
    for (int nb = 0; nb < 8; nb++)
#pragma unroll
        for (int j = 0; j < 4; j++) c[nb][j] = 0.0f;

    const int arow = warp * 16 + (lane >> 2);
    const char* aHbase = sm + AHI_OFF + arow * 144 + (lane & 3) * 4;
    const char* aLbase = sm + ALO_OFF + arow * 144 + (lane & 3) * 4;

#pragma unroll 1
    for (int t = 0; t < 9; t++) {
        __syncthreads();   // previous tap fully consumed
        // ---- A gather: 128 rows x 128B hi+lo, rows padded to 144B ----
        {
            int row = rbase + (t / 3 - 1) * PADW + (t % 3 - 1);
            const uint4* srcH = (const uint4*)(g_x_hi + ((size_t)row << 6)) + (half << 2);
            const uint4* srcL = (const uint4*)(g_x_lo + ((size_t)row << 6)) + (half << 2);
            char* aH = sm + AHI_OFF + myrow * 144 + half * 64;
            char* aL = sm + ALO_OFF + myrow * 144 + half * 64;
#pragma unroll
            for (int i = 0; i < 4; i++) {
                *(uint4*)(aH + i * 16) = srcH[i];
                *(uint4*)(aL + i * 16) = srcL[i];
            }
        }
        // ---- B stage: 8KB hi + 8KB lo of pre-permuted fragments ----
        {
            uint4* bH = (uint4*)(sm + BHI_OFF);
            uint4* bL = (uint4*)(sm + BLO_OFF);
#pragma unroll
            for (int i = 0; i < 2; i++) {
                int j = tid + (i << 8);
                bH[j] = wfh4[t * 512 + j];
                bL[j] = wfl4[t * 512 + j];
            }
        }
        __syncthreads();

        // ---- compute: 4 k-chunks x 8 n-blocks x 3 passes ----
#pragma unroll
        for (int kc = 0; kc < 4; kc++) {
            unsigned ah[4], al[4];
            const char* pH = aHbase + kc * 32;
            const char* pL = aLbase + kc * 32;
            ah[0] = *(const unsigned*)(pH);
            ah[1] = *(const unsigned*)(pH + 8 * 144);
            ah[2] = *(const unsigned*)(pH + 16);
            ah[3] = *(const unsigned*)(pH + 8 * 144 + 16);
            al[0] = *(const unsigned*)(pL);
            al[1] = *(const unsigned*)(pL + 8 * 144);
            al[2] = *(const unsigned*)(pL + 16);
            al[3] = *(const unsigned*)(pL + 8 * 144 + 16);
            const uint2* bHf = (const uint2*)(sm + BHI_OFF) + (kc * 8) * 32 + lane;
            const uint2* bLf = (const uint2*)(sm + BLO_OFF) + (kc * 8) * 32 + lane;
#pragma unroll
            for (int nb = 0; nb < 8; nb++) {
                uint2 bh = bHf[nb * 32];
                uint2 bl = bLf[nb * 32];
                MMA(c[nb], ah, bh.x, bh.y);
                MMA(c[nb], ah, bl.x, bl.y);
                MMA(c[nb], al, bh.x, bh.y);
            }
        }
    }

    // ---- epilogue: gate-weight * (acc + bias) -> atomicAdd ----
    {
        int g = lane >> 2, i4 = lane & 3;
        int r1 = warp * 16 + g, r2 = r1 + 8;
        bool v1 = r1 < m, v2 = r2 < m;
        int pix1 = v1 ? g_listPix[lb + r1] : 0;
        int pix2 = v2 ? g_listPix[lb + r2] : 0;
        float gw1 = ((float*)(sm + GW_OFF))[r1];
        float gw2 = ((float*)(sm + GW_OFF))[r2];
        float* op1 = out + ((size_t)(pix1 >> 14) << 20) + (pix1 & (HW - 1));
        float* op2 = out + ((size_t)(pix2 >> 14) << 20) + (pix2 & (HW - 1));
        const float* bias = (const float*)(sm + BIAS_OFF);
#pragma unroll
        for (int nb = 0; nb < 8; nb++) {
            int co = nb * 8 + 2 * i4;
            if (v1) {
                atomicAdd(op1 + ((size_t)co << 14),       gw1 * (c[nb][0] + bias[co]));
                atomicAdd(op1 + ((size_t)(co + 1) << 14), gw1 * (c[nb][1] + bias[co + 1]));
            }
            if (v2) {
                atomicAdd(op2 + ((size_t)co << 14),       gw2 * (c[nb][2] + bias[co]));
                atomicAdd(op2 + ((size_t)(co + 1) << 14), gw2 * (c[nb][3] + bias[co + 1]));
            }
        }
    }
}

// ---------------- relu ----------------
__global__ void k_relu(float* out, int n) {
    int i = blockIdx.x * 256 + threadIdx.x;
    if (i < n) out[i] = fmaxf(out[i], 0.0f);
}

extern "C" void kernel_launch(void* const* d_in, const int* in_sizes, int n_in,
                              void* d_out, int out_size) {
    const float* x        = (const float*)d_in[0];
    const float* expert_w = (const float*)d_in[1];
    const float* expert_b = (const float*)d_in[2];
    const float* gate_w   = (const float*)d_in[3];
    const float* gate_b   = (const float*)d_in[4];
    float* out = (float*)d_out;

    cudaFuncSetAttribute(k_conv, cudaFuncAttributeMaxDynamicSharedMemorySize,
                         CONV_SMEM);

    int n = NPIX * CC;

    k_init<<<(n + 255) / 256, 256>>>(out, n);
    k_tx<<<dim3(HW / 32, BB), dim3(32, 8)>>>(x);
    k_border<<<(NPADROW * 32 + 255) / 256, 256>>>();
    k_tw<<<(EE * WFE + 255) / 256, 256>>>(expert_w);
    k_gate<<<NPIX / 256, 256>>>(x, gate_w, gate_b);
    k_prefix<<<1, 32>>>();
    k_scatter<<<NPIX / 256, 256>>>();
    k_conv<<<MAXTILES, 256, CONV_SMEM>>>(expert_b, out);
    k_relu<<<(n + 255) / 256, 256>>>(out, n);
}